// round 1
// baseline (speedup 1.0000x reference)
#include <cuda_runtime.h>
#include <cuda_bf16.h>
#include <math.h>

// Problem constants
#define BATCH 2
#define SLEN  2048
#define TCOUNT 4096      // BATCH*SLEN
#define MDIM  1024
#define NHEAD 16
#define DHEAD 64
#define NQKV  3072
#define DFFN  4096
#define NEXP  8
#define NASSIGN 8192     // TCOUNT * TOP_K

// ---------------- scratch (static device globals; no runtime alloc) ----------
__device__ float g_h   [TCOUNT * MDIM];
__device__ float g_qkv [TCOUNT * NQKV];
__device__ float g_ctx [TCOUNT * MDIM];
__device__ float g_y   [TCOUNT * MDIM];
__device__ float g_h2  [TCOUNT * MDIM];
__device__ float g_u   [NASSIGN * DFFN];
__device__ float g_g3  [NASSIGN * DFFN];
__device__ float g_moe [2 * TCOUNT * MDIM];
__device__ float g_topw[TCOUNT * 2];
__device__ int   g_topi[TCOUNT * 2];
__device__ int   g_cnt [NEXP];
__device__ int   g_base[NEXP];
__device__ int   g_fill[NEXP];
__device__ int   g_assign[NASSIGN];

// ---------------- helpers ----------------------------------------------------
__device__ __forceinline__ float warp_sum(float v) {
    #pragma unroll
    for (int o = 16; o; o >>= 1) v += __shfl_xor_sync(0xffffffffu, v, o);
    return v;
}

// ---------------- LayerNorm: one block per row -------------------------------
__global__ void ln_kernel(const float* __restrict__ x,
                          const float* __restrict__ g,
                          const float* __restrict__ b,
                          float* __restrict__ out) {
    int t = blockIdx.x;
    const float* xr = x + (size_t)t * MDIM;
    int tid = threadIdx.x;
    float v[4];
    float s = 0.f, s2 = 0.f;
    #pragma unroll
    for (int i = 0; i < 4; i++) {
        v[i] = xr[tid + 256 * i];
        s += v[i];
        s2 += v[i] * v[i];
    }
    __shared__ float rs[8], rs2[8];
    s = warp_sum(s); s2 = warp_sum(s2);
    if ((tid & 31) == 0) { rs[tid >> 5] = s; rs2[tid >> 5] = s2; }
    __syncthreads();
    if (tid < 32) {
        float a = (tid < 8) ? rs[tid] : 0.f;
        float a2 = (tid < 8) ? rs2[tid] : 0.f;
        a = warp_sum(a); a2 = warp_sum(a2);
        if (tid == 0) { rs[0] = a; rs2[0] = a2; }
    }
    __syncthreads();
    float mean = rs[0] * (1.f / MDIM);
    float var  = rs2[0] * (1.f / MDIM) - mean * mean;
    float inv  = rsqrtf(var + 1e-5f);
    float* orow = out + (size_t)t * MDIM;
    #pragma unroll
    for (int i = 0; i < 4; i++) {
        int c = tid + 256 * i;
        orow[c] = (v[i] - mean) * inv * g[c] + b[c];
    }
}

// ---------------- generic NT SGEMM: C = A(MxK) @ W(NxK)^T (+bias)(+res) ------
// 128x128 tile, BK=8, 256 threads, 8x8 microtile.
__global__ void gemm_bias_res(const float* __restrict__ A,
                              const float* __restrict__ W,
                              const float* __restrict__ bias,
                              const float* __restrict__ res,
                              float* __restrict__ C,
                              int N, int K) {
    __shared__ float As[8][129];
    __shared__ float Bs[8][129];
    int n0 = blockIdx.x * 128;
    int m0 = blockIdx.y * 128;
    int tid = threadIdx.x;
    int tx = tid & 15, ty = tid >> 4;
    int lrow = tid >> 1, kq = (tid & 1) * 4;
    const float* aptr = A + (size_t)(m0 + lrow) * K + kq;
    const float* bptr = W + (size_t)(n0 + lrow) * K + kq;

    float acc[8][8];
    #pragma unroll
    for (int i = 0; i < 8; i++)
        #pragma unroll
        for (int j = 0; j < 8; j++) acc[i][j] = 0.f;

    for (int k0 = 0; k0 < K; k0 += 8) {
        float4 av = *(const float4*)(aptr + k0);
        float4 bv = *(const float4*)(bptr + k0);
        __syncthreads();
        As[kq + 0][lrow] = av.x; As[kq + 1][lrow] = av.y;
        As[kq + 2][lrow] = av.z; As[kq + 3][lrow] = av.w;
        Bs[kq + 0][lrow] = bv.x; Bs[kq + 1][lrow] = bv.y;
        Bs[kq + 2][lrow] = bv.z; Bs[kq + 3][lrow] = bv.w;
        __syncthreads();
        #pragma unroll
        for (int k = 0; k < 8; k++) {
            float a[8], bb[8];
            #pragma unroll
            for (int i = 0; i < 8; i++) a[i] = As[k][ty + 16 * i];
            #pragma unroll
            for (int j = 0; j < 8; j++) bb[j] = Bs[k][tx + 16 * j];
            #pragma unroll
            for (int i = 0; i < 8; i++)
                #pragma unroll
                for (int j = 0; j < 8; j++) acc[i][j] += a[i] * bb[j];
        }
    }
    #pragma unroll
    for (int i = 0; i < 8; i++) {
        int m = m0 + ty + 16 * i;
        #pragma unroll
        for (int j = 0; j < 8; j++) {
            int n = n0 + tx + 16 * j;
            float v = acc[i][j] + bias[n];
            if (res) v += res[(size_t)m * N + n];
            C[(size_t)m * N + n] = v;
        }
    }
}

// ---------------- MoE input GEMM: rows gathered per expert -------------------
// C[base+row] = h2[token(row)] @ W[e]^T   (W: [E][DFFN][MDIM])
__global__ void gemm_moe_in(const float* __restrict__ A,
                            const float* __restrict__ W,
                            float* __restrict__ C) {
    int e = blockIdx.z;
    int cnt = g_cnt[e];
    int m0 = blockIdx.y * 128;
    if (m0 >= cnt) return;
    int base = g_base[e];
    int n0 = blockIdx.x * 128;
    const float* We = W + (size_t)e * DFFN * MDIM;

    __shared__ float As[8][129];
    __shared__ float Bs[8][129];
    int tid = threadIdx.x;
    int tx = tid & 15, ty = tid >> 4;
    int lrow = tid >> 1, kq = (tid & 1) * 4;

    int lr = m0 + lrow;
    int lr_c = lr < cnt ? lr : cnt - 1;
    int tok = g_assign[base + lr_c] >> 1;
    const float* aptr = A + (size_t)tok * MDIM + kq;
    const float* bptr = We + (size_t)(n0 + lrow) * MDIM + kq;

    float acc[8][8];
    #pragma unroll
    for (int i = 0; i < 8; i++)
        #pragma unroll
        for (int j = 0; j < 8; j++) acc[i][j] = 0.f;

    for (int k0 = 0; k0 < MDIM; k0 += 8) {
        float4 av = *(const float4*)(aptr + k0);
        float4 bv = *(const float4*)(bptr + k0);
        __syncthreads();
        As[kq + 0][lrow] = av.x; As[kq + 1][lrow] = av.y;
        As[kq + 2][lrow] = av.z; As[kq + 3][lrow] = av.w;
        Bs[kq + 0][lrow] = bv.x; Bs[kq + 1][lrow] = bv.y;
        Bs[kq + 2][lrow] = bv.z; Bs[kq + 3][lrow] = bv.w;
        __syncthreads();
        #pragma unroll
        for (int k = 0; k < 8; k++) {
            float a[8], bb[8];
            #pragma unroll
            for (int i = 0; i < 8; i++) a[i] = As[k][ty + 16 * i];
            #pragma unroll
            for (int j = 0; j < 8; j++) bb[j] = Bs[k][tx + 16 * j];
            #pragma unroll
            for (int i = 0; i < 8; i++)
                #pragma unroll
                for (int j = 0; j < 8; j++) acc[i][j] += a[i] * bb[j];
        }
    }
    #pragma unroll
    for (int i = 0; i < 8; i++) {
        int m = m0 + ty + 16 * i;
        if (m < cnt) {
            float* cr = C + (size_t)(base + m) * DFFN + n0;
            #pragma unroll
            for (int j = 0; j < 8; j++) cr[tx + 16 * j] = acc[i][j];
        }
    }
}

// ---------------- MoE output GEMM: act @ w2[e]^T, scaled scatter -------------
__global__ void gemm_moe_out(const float* __restrict__ A,   // g_u (act)
                             const float* __restrict__ W) { // w2: [E][MDIM][DFFN]
    int e = blockIdx.z;
    int cnt = g_cnt[e];
    int m0 = blockIdx.y * 128;
    if (m0 >= cnt) return;
    int base = g_base[e];
    int n0 = blockIdx.x * 128;
    const float* We = W + (size_t)e * MDIM * DFFN;

    __shared__ float As[8][129];
    __shared__ float Bs[8][129];
    int tid = threadIdx.x;
    int tx = tid & 15, ty = tid >> 4;
    int lrow = tid >> 1, kq = (tid & 1) * 4;

    int lr = m0 + lrow;
    int lr_c = lr < cnt ? lr : cnt - 1;
    const float* aptr = A + (size_t)(base + lr_c) * DFFN + kq;
    const float* bptr = We + (size_t)(n0 + lrow) * DFFN + kq;

    float acc[8][8];
    #pragma unroll
    for (int i = 0; i < 8; i++)
        #pragma unroll
        for (int j = 0; j < 8; j++) acc[i][j] = 0.f;

    for (int k0 = 0; k0 < DFFN; k0 += 8) {
        float4 av = *(const float4*)(aptr + k0);
        float4 bv = *(const float4*)(bptr + k0);
        __syncthreads();
        As[kq + 0][lrow] = av.x; As[kq + 1][lrow] = av.y;
        As[kq + 2][lrow] = av.z; As[kq + 3][lrow] = av.w;
        Bs[kq + 0][lrow] = bv.x; Bs[kq + 1][lrow] = bv.y;
        Bs[kq + 2][lrow] = bv.z; Bs[kq + 3][lrow] = bv.w;
        __syncthreads();
        #pragma unroll
        for (int k = 0; k < 8; k++) {
            float a[8], bb[8];
            #pragma unroll
            for (int i = 0; i < 8; i++) a[i] = As[k][ty + 16 * i];
            #pragma unroll
            for (int j = 0; j < 8; j++) bb[j] = Bs[k][tx + 16 * j];
            #pragma unroll
            for (int i = 0; i < 8; i++)
                #pragma unroll
                for (int j = 0; j < 8; j++) acc[i][j] += a[i] * bb[j];
        }
    }
    #pragma unroll
    for (int i = 0; i < 8; i++) {
        int m = m0 + ty + 16 * i;
        if (m < cnt) {
            int a = g_assign[base + m];
            int tok = a >> 1;
            int slot = a & 1;
            float wgt = g_topw[tok * 2 + slot];
            float* cr = g_moe + (size_t)slot * TCOUNT * MDIM + (size_t)tok * MDIM + n0;
            #pragma unroll
            for (int j = 0; j < 8; j++) cr[tx + 16 * j] = wgt * acc[i][j];
        }
    }
}

// ---------------- flash attention (causal, no scale, fp32) -------------------
// block = (q-tile 64, head, batch), 256 threads, 4x4 microtile on 64x64 tiles.
#define ATT_SMEM (4 * 64 * 65 * 4)
__global__ void attn_kernel(const float* __restrict__ qkv, float* __restrict__ ctx) {
    extern __shared__ float sm[];
    float* Qs = sm;
    float* Ks = Qs + 64 * 65;
    float* Vs = Ks + 64 * 65;
    float* Ps = Vs + 64 * 65;
    int qt = blockIdx.x, h = blockIdx.y, b = blockIdx.z;
    int t = threadIdx.x;
    int tx = t & 15, ty = t >> 4;
    int r0 = ty * 4;

    const float* qbase = qkv + ((size_t)(b * SLEN + qt * 64)) * NQKV + h * DHEAD;
    for (int i = t; i < 64 * 64; i += 256) {
        int r = i >> 6, d = i & 63;
        Qs[r * 65 + d] = qbase[(size_t)r * NQKV + d];
    }

    float m[4], l[4], O[4][4];
    #pragma unroll
    for (int i = 0; i < 4; i++) {
        m[i] = -1e30f; l[i] = 0.f;
        #pragma unroll
        for (int j = 0; j < 4; j++) O[i][j] = 0.f;
    }

    for (int jt = 0; jt <= qt; jt++) {
        __syncthreads();
        const float* kbase = qkv + ((size_t)(b * SLEN + jt * 64)) * NQKV + MDIM + h * DHEAD;
        const float* vbase = kbase + MDIM;
        for (int i = t; i < 64 * 64; i += 256) {
            int r = i >> 6, d = i & 63;
            Ks[r * 65 + d] = kbase[(size_t)r * NQKV + d];
            Vs[r * 65 + d] = vbase[(size_t)r * NQKV + d];
        }
        __syncthreads();

        float S[4][4];
        #pragma unroll
        for (int i = 0; i < 4; i++)
            #pragma unroll
            for (int j = 0; j < 4; j++) S[i][j] = 0.f;
        for (int d = 0; d < 64; d++) {
            float a[4], bb[4];
            #pragma unroll
            for (int i = 0; i < 4; i++) a[i] = Qs[(r0 + i) * 65 + d];
            #pragma unroll
            for (int j = 0; j < 4; j++) bb[j] = Ks[(tx + 16 * j) * 65 + d];
            #pragma unroll
            for (int i = 0; i < 4; i++)
                #pragma unroll
                for (int j = 0; j < 4; j++) S[i][j] += a[i] * bb[j];
        }
        if (jt == qt) {
            #pragma unroll
            for (int i = 0; i < 4; i++)
                #pragma unroll
                for (int j = 0; j < 4; j++)
                    if (tx + 16 * j > r0 + i) S[i][j] = -1e30f;
        }
        #pragma unroll
        for (int i = 0; i < 4; i++) {
            float tm = S[i][0];
            #pragma unroll
            for (int j = 1; j < 4; j++) tm = fmaxf(tm, S[i][j]);
            #pragma unroll
            for (int o = 8; o >= 1; o >>= 1)
                tm = fmaxf(tm, __shfl_xor_sync(0xffffffffu, tm, o, 16));
            float newm = fmaxf(m[i], tm);
            float scl = __expf(m[i] - newm);
            float rs = 0.f;
            #pragma unroll
            for (int j = 0; j < 4; j++) {
                S[i][j] = __expf(S[i][j] - newm);
                rs += S[i][j];
            }
            #pragma unroll
            for (int o = 8; o >= 1; o >>= 1)
                rs += __shfl_xor_sync(0xffffffffu, rs, o, 16);
            l[i] = l[i] * scl + rs;
            m[i] = newm;
            #pragma unroll
            for (int j = 0; j < 4; j++) {
                O[i][j] *= scl;
                Ps[(r0 + i) * 65 + tx + 16 * j] = S[i][j];
            }
        }
        __syncthreads();
        for (int c = 0; c < 64; c++) {
            float p[4], v[4];
            #pragma unroll
            for (int i = 0; i < 4; i++) p[i] = Ps[(r0 + i) * 65 + c];
            #pragma unroll
            for (int j = 0; j < 4; j++) v[j] = Vs[c * 65 + tx + 16 * j];
            #pragma unroll
            for (int i = 0; i < 4; i++)
                #pragma unroll
                for (int j = 0; j < 4; j++) O[i][j] += p[i] * v[j];
        }
    }

    float* obase = ctx + ((size_t)(b * SLEN + qt * 64)) * MDIM + h * DHEAD;
    #pragma unroll
    for (int i = 0; i < 4; i++) {
        float invl = 1.f / l[i];
        #pragma unroll
        for (int j = 0; j < 4; j++)
            obase[(size_t)(r0 + i) * MDIM + tx + 16 * j] = O[i][j] * invl;
    }
}

// ---------------- routing: gate logits, softmax, top-2 -----------------------
__global__ void route_kernel(const float* __restrict__ h2,
                             const float* __restrict__ gw) {
    int t = blockIdx.x * 8 + (threadIdx.x >> 5);
    int lane = threadIdx.x & 31;
    if (t >= TCOUNT) return;
    const float* hr = h2 + (size_t)t * MDIM;
    float acc[NEXP];
    #pragma unroll
    for (int e = 0; e < NEXP; e++) acc[e] = 0.f;
    for (int i = lane; i < MDIM; i += 32) {
        float hv = hr[i];
        #pragma unroll
        for (int e = 0; e < NEXP; e++) acc[e] += hv * gw[e * MDIM + i];
    }
    #pragma unroll
    for (int e = 0; e < NEXP; e++) acc[e] = warp_sum(acc[e]);
    if (lane == 0) {
        float mx = acc[0];
        #pragma unroll
        for (int e = 1; e < NEXP; e++) mx = fmaxf(mx, acc[e]);
        float ex[NEXP];
        #pragma unroll
        for (int e = 0; e < NEXP; e++) ex[e] = __expf(acc[e] - mx);
        int i0 = 0;
        #pragma unroll
        for (int e = 1; e < NEXP; e++) if (acc[e] > acc[i0]) i0 = e;
        int i1 = (i0 == 0) ? 1 : 0;
        #pragma unroll
        for (int e = 0; e < NEXP; e++)
            if (e != i0 && acc[e] > acc[i1]) i1 = e;
        float denom = 1.f / (ex[i0] + ex[i1]);
        g_topi[t * 2 + 0] = i0;
        g_topi[t * 2 + 1] = i1;
        g_topw[t * 2 + 0] = ex[i0] * denom;
        g_topw[t * 2 + 1] = ex[i1] * denom;
        atomicAdd(&g_cnt[i0], 1);
        atomicAdd(&g_cnt[i1], 1);
    }
}

__global__ void prefix_kernel() {
    if (threadIdx.x == 0 && blockIdx.x == 0) {
        int acc = 0;
        for (int e = 0; e < NEXP; e++) {
            g_base[e] = acc;
            acc += g_cnt[e];
            g_fill[e] = 0;
        }
    }
}

__global__ void assign_kernel() {
    int t = blockIdx.x * blockDim.x + threadIdx.x;
    if (t < TCOUNT) {
        #pragma unroll
        for (int s = 0; s < 2; s++) {
            int e = g_topi[t * 2 + s];
            int pos = g_base[e] + atomicAdd(&g_fill[e], 1);
            g_assign[pos] = t * 2 + s;
        }
    }
}

// ---------------- elementwise -------------------------------------------------
__global__ void silu_mul_kernel(float* __restrict__ u,
                                const float* __restrict__ g3, int n) {
    for (int i = blockIdx.x * blockDim.x + threadIdx.x; i < n;
         i += gridDim.x * blockDim.x) {
        float a = u[i];
        float s = a / (1.f + __expf(-a));
        u[i] = s * g3[i];
    }
}

__global__ void final_add_kernel(const float* __restrict__ y,
                                 float* __restrict__ out, int n) {
    for (int i = blockIdx.x * blockDim.x + threadIdx.x; i < n;
         i += gridDim.x * blockDim.x) {
        out[i] = y[i] + g_moe[i] + g_moe[(size_t)TCOUNT * MDIM + i];
    }
}

// ---------------- launch ------------------------------------------------------
extern "C" void kernel_launch(void* const* d_in, const int* in_sizes, int n_in,
                              void* d_out, int out_size) {
    const float* x     = (const float*)d_in[0];
    const float* ln1g  = (const float*)d_in[1];
    const float* ln1b  = (const float*)d_in[2];
    const float* qkvw  = (const float*)d_in[3];
    const float* qkvb  = (const float*)d_in[4];
    const float* ow    = (const float*)d_in[5];
    const float* ob    = (const float*)d_in[6];
    const float* ln2g  = (const float*)d_in[7];
    const float* ln2b  = (const float*)d_in[8];
    const float* gatew = (const float*)d_in[9];
    const float* w1    = (const float*)d_in[10];
    const float* w2    = (const float*)d_in[11];
    const float* w3    = (const float*)d_in[12];
    float* out = (float*)d_out;

    cudaFuncSetAttribute(attn_kernel,
                         cudaFuncAttributeMaxDynamicSharedMemorySize, ATT_SMEM);

    void* cntp = nullptr;
    cudaGetSymbolAddress(&cntp, g_cnt);
    cudaMemsetAsync(cntp, 0, sizeof(int) * NEXP);

    // 1) h = LN1(x)
    ln_kernel<<<TCOUNT, 256>>>(x, ln1g, ln1b, g_h);
    // 2) qkv = h @ qkvw^T + qkvb
    gemm_bias_res<<<dim3(NQKV / 128, TCOUNT / 128), 256>>>(
        g_h, qkvw, qkvb, nullptr, g_qkv, NQKV, MDIM);
    // 3) causal attention
    attn_kernel<<<dim3(SLEN / 64, NHEAD, BATCH), 256, ATT_SMEM>>>(g_qkv, g_ctx);
    // 4) y = x + ctx @ ow^T + ob
    gemm_bias_res<<<dim3(MDIM / 128, TCOUNT / 128), 256>>>(
        g_ctx, ow, ob, x, g_y, MDIM, MDIM);
    // 5) h2 = LN2(y)
    ln_kernel<<<TCOUNT, 256>>>(g_y, ln2g, ln2b, g_h2);
    // 6) routing
    route_kernel<<<TCOUNT / 8, 256>>>(g_h2, gatew);
    prefix_kernel<<<1, 32>>>();
    assign_kernel<<<TCOUNT / 256, 256>>>();
    // 7) u = h2g @ w1^T ; g3 = h2g @ w3^T   (gathered rows, per expert)
    gemm_moe_in<<<dim3(DFFN / 128, NASSIGN / 128, NEXP), 256>>>(g_h2, w1, g_u);
    gemm_moe_in<<<dim3(DFFN / 128, NASSIGN / 128, NEXP), 256>>>(g_h2, w3, g_g3);
    // 8) act = silu(u) * g3  (in place into g_u)
    silu_mul_kernel<<<4096, 256>>>(g_u, g_g3, NASSIGN * DFFN);
    // 9) moe_out[slot][tok] = w * (act @ w2^T)
    gemm_moe_out<<<dim3(MDIM / 128, NASSIGN / 128, NEXP), 256>>>(g_u, w2);
    // 10) out = y + moe0 + moe1
    final_add_kernel<<<4096, 256>>>(g_y, out, TCOUNT * MDIM);
}